// round 13
// baseline (speedup 1.0000x reference)
#include <cuda_runtime.h>
#include <cuda_fp16.h>

// GridSampler3D: vol [8,32,64,64,64] fp32, grid [8,64,64,64,3], trilinear,
// zeros padding, align_corners=True. Output [8,32,64,64,64] fp32.
//
// Pipeline: 8 stages, 3 rotating 16MB fp16 NDHWC buffers, T on side stream.
// G restructured into 3 phases: coalesced grid->smem, per-point precompute
// (once, not 4x), lean gather loop (2 LDS + 2 LDG + 8 HFMA2 per row).

#define Nn 8
#define Cc 32
#define Dd 64
#define Hh 64
#define Ww 64
#define S  (Dd * Hh * Ww)   // 262144 = 2^18
#define NBUF 3

__device__ __half g_volt[NBUF][(size_t)S * Cc];   // 3 x 16 MB rotating buffers

// ---------------------------------------------------------------------------
// T(n): 4096 blocks; block = 256 threads handles 64 spatial x 32 channels.
// ---------------------------------------------------------------------------
__global__ void __launch_bounds__(256) transpose_to_nhwc_h(const float* __restrict__ voln,
                                                           int buf) {
    __shared__ float tile[64][33];
    const int s0  = blockIdx.x << 6;
    const int tid = threadIdx.x;
    __half* __restrict__ dst = g_volt[buf];

    {
        const int c  = tid >> 4;
        const int s4 = tid & 15;
        #pragma unroll
        for (int half_i = 0; half_i < 2; half_i++) {
            const int ch = c + half_i * 16;
            const float4 v = *(const float4*)(voln + (size_t)ch * S + s0 + s4 * 4);
            tile[s4 * 4 + 0][ch] = v.x;
            tile[s4 * 4 + 1][ch] = v.y;
            tile[s4 * 4 + 2][ch] = v.z;
            tile[s4 * 4 + 3][ch] = v.w;
        }
    }
    __syncthreads();

    {
        const int s  = tid >> 3;
        const int c4 = tid & 7;
        #pragma unroll
        for (int half_i = 0; half_i < 2; half_i++) {
            const int sp = s + half_i * 32;
            __half2 h0 = __floats2half2_rn(tile[sp][c4 * 4 + 0], tile[sp][c4 * 4 + 1]);
            __half2 h1 = __floats2half2_rn(tile[sp][c4 * 4 + 2], tile[sp][c4 * 4 + 3]);
            uint2 pk;
            pk.x = *(unsigned*)&h0;
            pk.y = *(unsigned*)&h1;
            *(uint2*)(dst + ((size_t)(s0 + sp)) * Cc + c4 * 4) = pk;
        }
    }
}

// ---------------------------------------------------------------------------
// G(n): 4096 blocks = 64 points each; 4 lanes/point, 8 channels/lane.
// ---------------------------------------------------------------------------
__global__ void __launch_bounds__(256, 8) grid_sample3d_kernel(const float* __restrict__ gridn,
                                                               float* __restrict__ outn,
                                                               int buf) {
    __shared__ float s_grid[192];            // 64 points x 3 coords
    __shared__ int   s_row[4][64];           // row element-offset per (r, point)
    __shared__ uint2 s_w[4][64];             // packed (wa, wb) half2 pair per (r, point)
    __shared__ int   s_xo0[64], s_xo1[64];   // x element-offsets per point
    __shared__ float s_tile[64][33];         // output staging [point][channel]

    const int tid = threadIdx.x;
    const int sb  = blockIdx.x * 64;         // block's first point

    // Phase 1: coalesced grid load.
    if (tid < 192) s_grid[tid] = gridn[sb * 3 + tid];
    __syncthreads();

    // Phase 2: per-point precompute (64 threads, once per point).
    if (tid < 64) {
        const float gx = s_grid[tid * 3 + 0];
        const float gy = s_grid[tid * 3 + 1];
        const float gz = s_grid[tid * 3 + 2];

        const float ix = (gx + 1.0f) * (0.5f * (Ww - 1));
        const float iy = (gy + 1.0f) * (0.5f * (Hh - 1));
        const float iz = (gz + 1.0f) * (0.5f * (Dd - 1));

        const float fx = floorf(ix), fy = floorf(iy), fz = floorf(iz);
        const int x0 = (int)fx, y0 = (int)fy, z0 = (int)fz;
        const float wx1 = ix - fx, wy1 = iy - fy, wz1 = iz - fz;

        // coords in [0,63]; clamped corner -> weight exactly 0 == zero padding.
        const int x1 = min(x0 + 1, Ww - 1);
        const int y1 = min(y0 + 1, Hh - 1);
        const int z1 = min(z0 + 1, Dd - 1);

        const float wx0 = 1.0f - wx1, wy0 = 1.0f - wy1, wz0 = 1.0f - wz1;
        const float wzy[4] = {wz0 * wy0, wz0 * wy1, wz1 * wy0, wz1 * wy1};
        const int ys2[2] = {y0, y1};
        const int zs2[2] = {z0, z1};

        #pragma unroll
        for (int r = 0; r < 4; r++) {
            const int zi = zs2[r >> 1];
            const int yi = ys2[r & 1];
            s_row[r][tid] = (((zi << 6) + yi) << 6) << 5;     // ((z*H+y)*W)*C
            const __half2 wa = __float2half2_rn(wzy[r] * wx0);
            const __half2 wb = __float2half2_rn(wzy[r] * wx1);
            uint2 pk;
            pk.x = *(const unsigned*)&wa;
            pk.y = *(const unsigned*)&wb;
            s_w[r][tid] = pk;
        }
        s_xo0[tid] = x0 << 5;
        s_xo1[tid] = x1 << 5;
    }
    __syncthreads();

    // Phase 3: lean gather loop. 4 lanes/point, 8 channels/lane.
    const int pl = tid >> 2;                 // point 0..63
    const int c4 = tid & 3;                  // channel octet 0..3
    const __half* __restrict__ vtc = g_volt[buf] + c4 * 8;
    const int xo0 = s_xo0[pl];
    const int xo1 = s_xo1[pl];

    __half2 accA[4], accB[4];
    #pragma unroll
    for (int j = 0; j < 4; j++) { accA[j] = __float2half2_rn(0.0f); accB[j] = accA[j]; }

    #pragma unroll
    for (int r = 0; r < 4; r++) {
        const int ro = s_row[r][pl];
        const uint2 wpk = s_w[r][pl];
        const __half2 wa = *(const __half2*)&wpk.x;
        const __half2 wb = *(const __half2*)&wpk.y;
        const uint4 a = *(const uint4*)(vtc + ro + xo0);
        const uint4 b = *(const uint4*)(vtc + ro + xo1);

        if (r < 2) {
            #pragma unroll
            for (int j = 0; j < 4; j++) {
                accA[j] = __hfma2(((const __half2*)&a)[j], wa, accA[j]);
                accA[j] = __hfma2(((const __half2*)&b)[j], wb, accA[j]);
            }
        } else {
            #pragma unroll
            for (int j = 0; j < 4; j++) {
                accB[j] = __hfma2(((const __half2*)&a)[j], wa, accB[j]);
                accB[j] = __hfma2(((const __half2*)&b)[j], wb, accB[j]);
            }
        }
    }

    #pragma unroll
    for (int j = 0; j < 4; j++) {
        const float2 f = __half22float2(__hadd2(accA[j], accB[j]));
        s_tile[pl][c4 * 8 + 2 * j + 0] = f.x;
        s_tile[pl][c4 * 8 + 2 * j + 1] = f.y;
    }
    __syncthreads();

    // Write outn[ch, sb + p]: warp = 32 consecutive points, coalesced 128B.
    const int wv  = tid >> 5;                // warp 0..7
    const int ln  = tid & 31;
    const int p   = (wv & 1) * 32 + ln;      // point 0..63
    const int chb = wv >> 1;                 // channel base 0..3
    float* __restrict__ o = outn + (size_t)sb + p;
    #pragma unroll
    for (int rep = 0; rep < 8; rep++) {
        const int ch = chb + rep * 4;
        o[(size_t)ch * S] = s_tile[p][ch];
    }
}

// ---------------------------------------------------------------------------
// Host pipeline: fork sT off the capture stream with events.
// ---------------------------------------------------------------------------
static cudaStream_t g_sT = nullptr;
static cudaEvent_t  g_eFork = nullptr;
static cudaEvent_t  g_eT[Nn];
static cudaEvent_t  g_eG[Nn];

extern "C" void kernel_launch(void* const* d_in, const int* in_sizes, int n_in,
                              void* d_out, int out_size) {
    const float* vol  = (const float*)d_in[0];   // [8,32,S]
    const float* grid = (const float*)d_in[1];   // [8,S,3]
    float* out = (float*)d_out;                  // [8,32,S]

    if (g_sT == nullptr) {                       // one-time resources (no device mem)
        cudaStreamCreateWithFlags(&g_sT, cudaStreamNonBlocking);
        cudaEventCreateWithFlags(&g_eFork, cudaEventDisableTiming);
        for (int i = 0; i < Nn; i++) {
            cudaEventCreateWithFlags(&g_eT[i], cudaEventDisableTiming);
            cudaEventCreateWithFlags(&g_eG[i], cudaEventDisableTiming);
        }
    }

    cudaEventRecord(g_eFork, 0);
    cudaStreamWaitEvent(g_sT, g_eFork, 0);

    for (int n = 0; n < Nn; n++) {
        const int buf = n % NBUF;
        if (n >= NBUF) cudaStreamWaitEvent(g_sT, g_eG[n - NBUF], 0);  // buffer reuse guard

        transpose_to_nhwc_h<<<S / 64, 256, 0, g_sT>>>(vol + (size_t)n * Cc * S, buf);
        cudaEventRecord(g_eT[n], g_sT);

        cudaStreamWaitEvent(0, g_eT[n], 0);      // G(n) after T(n)
        grid_sample3d_kernel<<<S / 64, 256>>>(grid + (size_t)n * S * 3,
                                              out + (size_t)n * Cc * S, buf);
        cudaEventRecord(g_eG[n], 0);
    }
}

// round 14
// speedup vs baseline: 1.0589x; 1.0589x over previous
#include <cuda_runtime.h>
#include <cuda_fp16.h>

// GridSampler3D: vol [8,32,64,64,64] fp32, grid [8,64,64,64,3], trilinear,
// zeros padding, align_corners=True. Output [8,32,64,64,64] fp32.
//
// Pipeline: 8 stages, 3 rotating 16MB fp16 NDHWC buffers.
//   sT:        T(n) transpose batch n into buf[n%3]
//   sG[n&1]:   G(n) gather batch n (consecutive G's overlap each other,
//              hiding per-launch ramp/tail)
// T(n) waits eG[n-3] (buffer reuse); G(n) waits eT[n]; capture stream joins
// on the last G of each G-stream.

#define Nn 8
#define Cc 32
#define Dd 64
#define Hh 64
#define Ww 64
#define S  (Dd * Hh * Ww)   // 262144 = 2^18
#define NBUF 3

__device__ __half g_volt[NBUF][(size_t)S * Cc];   // 3 x 16 MB rotating buffers

// ---------------------------------------------------------------------------
// T(n): 4096 blocks; block = 256 threads handles 64 spatial x 32 channels.
// ---------------------------------------------------------------------------
__global__ void __launch_bounds__(256) transpose_to_nhwc_h(const float* __restrict__ voln,
                                                           int buf) {
    __shared__ float tile[64][33];
    const int s0  = blockIdx.x << 6;
    const int tid = threadIdx.x;
    __half* __restrict__ dst = g_volt[buf];

    {
        const int c  = tid >> 4;
        const int s4 = tid & 15;
        #pragma unroll
        for (int half_i = 0; half_i < 2; half_i++) {
            const int ch = c + half_i * 16;
            const float4 v = *(const float4*)(voln + (size_t)ch * S + s0 + s4 * 4);
            tile[s4 * 4 + 0][ch] = v.x;
            tile[s4 * 4 + 1][ch] = v.y;
            tile[s4 * 4 + 2][ch] = v.z;
            tile[s4 * 4 + 3][ch] = v.w;
        }
    }
    __syncthreads();

    {
        const int s  = tid >> 3;
        const int c4 = tid & 7;
        #pragma unroll
        for (int half_i = 0; half_i < 2; half_i++) {
            const int sp = s + half_i * 32;
            __half2 h0 = __floats2half2_rn(tile[sp][c4 * 4 + 0], tile[sp][c4 * 4 + 1]);
            __half2 h1 = __floats2half2_rn(tile[sp][c4 * 4 + 2], tile[sp][c4 * 4 + 3]);
            uint2 pk;
            pk.x = *(unsigned*)&h0;
            pk.y = *(unsigned*)&h1;
            *(uint2*)(dst + ((size_t)(s0 + sp)) * Cc + c4 * 4) = pk;
        }
    }
}

// ---------------------------------------------------------------------------
// G(n): 4096 blocks; 4 lanes/point, 8 channels/lane; branch-free clamp;
// folded fp16 weights; 32-bit offset math; smem-staged coalesced writes.
// (Exact R12 form — best measured: 17.8us/batch.)
// ---------------------------------------------------------------------------
__global__ void __launch_bounds__(256, 8) grid_sample3d_kernel(const float* __restrict__ gridn,
                                                               float* __restrict__ outn,
                                                               int buf) {
    __shared__ float tile[64][33];           // [point][channel]

    const int tid = threadIdx.x;
    const int pl  = tid >> 2;                // point-in-block 0..63
    const int c4  = tid & 3;                 // channel octet 0..3

    const int t = blockIdx.x * 64 + pl;      // point id within batch

    const float gx = gridn[t * 3 + 0];
    const float gy = gridn[t * 3 + 1];
    const float gz = gridn[t * 3 + 2];

    const float ix = (gx + 1.0f) * (0.5f * (Ww - 1));
    const float iy = (gy + 1.0f) * (0.5f * (Hh - 1));
    const float iz = (gz + 1.0f) * (0.5f * (Dd - 1));

    const float fx = floorf(ix), fy = floorf(iy), fz = floorf(iz);
    const int x0 = (int)fx, y0 = (int)fy, z0 = (int)fz;
    const float wx1 = ix - fx, wy1 = iy - fy, wz1 = iz - fz;

    // coords in [0,63]; clamped corner -> weight exactly 0 == zero padding.
    const int x1 = min(x0 + 1, Ww - 1);
    const int y1 = min(y0 + 1, Hh - 1);
    const int z1 = min(z0 + 1, Dd - 1);

    const float wx0 = 1.0f - wx1, wy0 = 1.0f - wy1, wz0 = 1.0f - wz1;
    const float wzy[4] = {wz0 * wy0, wz0 * wy1, wz1 * wy0, wz1 * wy1};

    const int ys2[2] = {y0, y1};
    const int zs2[2] = {z0, z1};

    const __half* __restrict__ vt = g_volt[buf] + c4 * 8;
    const int xo0 = x0 << 5;                 // 32-bit element offsets
    const int xo1 = x1 << 5;

    __half2 acc[4];
    #pragma unroll
    for (int j = 0; j < 4; j++) acc[j] = __float2half2_rn(0.0f);

    #pragma unroll
    for (int r = 0; r < 4; r++) {
        const int zi = zs2[r >> 1];
        const int yi = ys2[r & 1];
        const int rowoff = (((zi << 6) + yi) << 6) << 5;   // ((z*H+y)*W)*C, 32-bit
        const uint4 a = *(const uint4*)(vt + rowoff + xo0);
        const uint4 b = *(const uint4*)(vt + rowoff + xo1);
        const __half2 wa = __float2half2_rn(wzy[r] * wx0);
        const __half2 wb = __float2half2_rn(wzy[r] * wx1);

        #pragma unroll
        for (int j = 0; j < 4; j++) {
            acc[j] = __hfma2(((const __half2*)&a)[j], wa, acc[j]);
            acc[j] = __hfma2(((const __half2*)&b)[j], wb, acc[j]);
        }
    }

    #pragma unroll
    for (int j = 0; j < 4; j++) {
        const float2 f = __half22float2(acc[j]);
        tile[pl][c4 * 8 + 2 * j + 0] = f.x;
        tile[pl][c4 * 8 + 2 * j + 1] = f.y;
    }
    __syncthreads();

    // Write outn[ch, sb + p]: warp = 32 consecutive points, coalesced 128B.
    const int wv  = tid >> 5;                // warp 0..7
    const int ln  = tid & 31;
    const int p   = (wv & 1) * 32 + ln;      // point 0..63
    const int chb = wv >> 1;                 // channel base 0..3
    const int sb  = blockIdx.x * 64;
    float* __restrict__ o = outn + (size_t)sb + p;
    #pragma unroll
    for (int rep = 0; rep < 8; rep++) {
        const int ch = chb + rep * 4;
        o[(size_t)ch * S] = tile[p][ch];
    }
}

// ---------------------------------------------------------------------------
// Host pipeline: T on sT, G alternating on sG[0]/sG[1]; event fork/join.
// ---------------------------------------------------------------------------
static cudaStream_t g_sT = nullptr;
static cudaStream_t g_sG[2] = {nullptr, nullptr};
static cudaEvent_t  g_eFork = nullptr;
static cudaEvent_t  g_eT[Nn];
static cudaEvent_t  g_eG[Nn];

extern "C" void kernel_launch(void* const* d_in, const int* in_sizes, int n_in,
                              void* d_out, int out_size) {
    const float* vol  = (const float*)d_in[0];   // [8,32,S]
    const float* grid = (const float*)d_in[1];   // [8,S,3]
    float* out = (float*)d_out;                  // [8,32,S]

    if (g_sT == nullptr) {                       // one-time resources (no device mem)
        cudaStreamCreateWithFlags(&g_sT, cudaStreamNonBlocking);
        cudaStreamCreateWithFlags(&g_sG[0], cudaStreamNonBlocking);
        cudaStreamCreateWithFlags(&g_sG[1], cudaStreamNonBlocking);
        cudaEventCreateWithFlags(&g_eFork, cudaEventDisableTiming);
        for (int i = 0; i < Nn; i++) {
            cudaEventCreateWithFlags(&g_eT[i], cudaEventDisableTiming);
            cudaEventCreateWithFlags(&g_eG[i], cudaEventDisableTiming);
        }
    }

    // Fork all worker streams from the capture (default) stream.
    cudaEventRecord(g_eFork, 0);
    cudaStreamWaitEvent(g_sT, g_eFork, 0);
    cudaStreamWaitEvent(g_sG[0], g_eFork, 0);
    cudaStreamWaitEvent(g_sG[1], g_eFork, 0);

    for (int n = 0; n < Nn; n++) {
        const int buf = n % NBUF;
        cudaStream_t sg = g_sG[n & 1];

        if (n >= NBUF) cudaStreamWaitEvent(g_sT, g_eG[n - NBUF], 0);  // buffer reuse guard

        transpose_to_nhwc_h<<<S / 64, 256, 0, g_sT>>>(vol + (size_t)n * Cc * S, buf);
        cudaEventRecord(g_eT[n], g_sT);

        cudaStreamWaitEvent(sg, g_eT[n], 0);     // G(n) after T(n)
        grid_sample3d_kernel<<<S / 64, 256, 0, sg>>>(grid + (size_t)n * S * 3,
                                                     out + (size_t)n * Cc * S, buf);
        cudaEventRecord(g_eG[n], sg);
    }

    // Join all worker streams back to the capture stream.
    cudaStreamWaitEvent(0, g_eG[Nn - 2], 0);
    cudaStreamWaitEvent(0, g_eG[Nn - 1], 0);
}